// round 3
// baseline (speedup 1.0000x reference)
#include <cuda_runtime.h>
#include <math.h>

#define B_TOTAL 16384
#define D_IN    512
#define HID     128
#define NTREE   64
#define NNODES  63
#define NCLS    10

// -------- scratch (device globals; no allocation allowed) --------
__device__ float g_xc[B_TOTAL * D_IN];      // NaN-cleaned x
__device__ int   g_missing[B_TOTAL];        // any-NaN per row
__device__ float g_attn[NTREE * B_TOTAL];   // [t][b] = softmax(attn)*0.3*resw[t]

// ================= kernel 0: clean NaNs =================
__global__ void k_clean(const float* __restrict__ x) {
    int row = blockIdx.x;
    int q = threadIdx.x;  // 128 quads of 4 floats = 512
    __shared__ int flag;
    if (q == 0) flag = 0;
    __syncthreads();
    float4 v = reinterpret_cast<const float4*>(x)[row * 128 + q];
    int m = 0;
    if (v.x != v.x) { v.x = 0.f; m = 1; }
    if (v.y != v.y) { v.y = 0.f; m = 1; }
    if (v.z != v.z) { v.z = 0.f; m = 1; }
    if (v.w != v.w) { v.w = 0.f; m = 1; }
    if (m) atomicOr(&flag, 1);
    reinterpret_cast<float4*>(g_xc)[row * 128 + q] = v;
    __syncthreads();
    if (q == 0) g_missing[row] = flag;
}

// ================= kernel A: attention =================
// CTA = 64 rows, 256 threads. Phase1: h = BN(relu(x@W1+b1)); Phase2: logits = h@W2+b2;
// row softmax -> g_attn[t][b] = attn * (0.3*resw[t])
__global__ __launch_bounds__(256) void k_attn(
    const float* __restrict__ x,
    const float* __restrict__ w1, const float* __restrict__ b1,
    const float* __restrict__ gamma_, const float* __restrict__ beta_,
    const float* __restrict__ mean_, const float* __restrict__ var_,
    const float* __restrict__ w2, const float* __restrict__ b2,
    const float* __restrict__ resw)
{
    __shared__ __align__(16) char smem[33792];
    float4* xs4  = reinterpret_cast<float4*>(smem);           // [64][9] quads (32 k)
    float*  xsf  = reinterpret_cast<float*>(smem);
    float4* w1s4 = reinterpret_cast<float4*>(smem + 9216);    // [32][33] quads
    float4* hs4  = reinterpret_cast<float4*>(smem);           // phase2: [64][33] quads
    float*  hsf  = reinterpret_cast<float*>(smem);
    float*  ls   = reinterpret_cast<float*>(smem);            // softmax: [64][68] floats

    const int tx = threadIdx.x;
    const int row0 = blockIdx.x * 64;
    const int ct = tx & 15, rt = tx >> 4;    // 16 col-groups x 16 row-groups
    const int c0 = ct * 8,  r0 = rt * 4;     // 8 cols, 4 rows per thread

    float acc[4][8];
#pragma unroll
    for (int i = 0; i < 4; ++i)
#pragma unroll
        for (int j = 0; j < 8; ++j) acc[i][j] = 0.f;

    const float4* x4  = reinterpret_cast<const float4*>(x);
    const float4* w14 = reinterpret_cast<const float4*>(w1);

    for (int kc = 0; kc < 16; ++kc) {        // K chunks of 32
#pragma unroll
        for (int j = 0; j < 2; ++j) {        // xs: 64 rows x 8 quads
            int idx = tx + 256 * j;
            int r = idx >> 3, q = idx & 7;
            xs4[r * 9 + q] = x4[(row0 + r) * 128 + kc * 8 + q];
        }
#pragma unroll
        for (int j = 0; j < 4; ++j) {        // w1: 32 k-rows x 32 quads
            int idx = tx + 256 * j;
            int k = idx >> 5, cq = idx & 31;
            w1s4[k * 33 + cq] = w14[(kc * 32 + k) * 32 + cq];
        }
        __syncthreads();
#pragma unroll 4
        for (int kk = 0; kk < 32; ++kk) {
            float4 bq0 = w1s4[kk * 33 + ct * 2];
            float4 bq1 = w1s4[kk * 33 + ct * 2 + 1];
#pragma unroll
            for (int i = 0; i < 4; ++i) {
                float a = xsf[(r0 + i) * 36 + kk];
                acc[i][0] += a * bq0.x; acc[i][1] += a * bq0.y;
                acc[i][2] += a * bq0.z; acc[i][3] += a * bq0.w;
                acc[i][4] += a * bq1.x; acc[i][5] += a * bq1.y;
                acc[i][6] += a * bq1.z; acc[i][7] += a * bq1.w;
            }
        }
        __syncthreads();
    }

    // epilogue: +b1, relu, BN -> hs (aliases xs/w1s; safe after final sync)
    float sc[8], sh[8], bb[8];
#pragma unroll
    for (int j = 0; j < 8; ++j) {
        int c = c0 + j;
        float s = gamma_[c] * rsqrtf(var_[c] + 1e-5f);
        sc[j] = s;
        sh[j] = beta_[c] - mean_[c] * s;
        bb[j] = b1[c];
    }
#pragma unroll
    for (int i = 0; i < 4; ++i) {
        float h[8];
#pragma unroll
        for (int j = 0; j < 8; ++j) {
            float v = fmaxf(acc[i][j] + bb[j], 0.f);
            h[j] = v * sc[j] + sh[j];
        }
        hs4[(r0 + i) * 33 + ct * 2]     = make_float4(h[0], h[1], h[2], h[3]);
        hs4[(r0 + i) * 33 + ct * 2 + 1] = make_float4(h[4], h[5], h[6], h[7]);
    }
    __syncthreads();

    // phase 2: logits2[64][64] = hs @ W2 + b2
    const int tt = tx & 15, rt2 = tx >> 4;
    const int t0 = tt * 4, r0b = rt2 * 4;
    float a2[4][4];
#pragma unroll
    for (int i = 0; i < 4; ++i)
#pragma unroll
        for (int j = 0; j < 4; ++j) a2[i][j] = b2[t0 + j];
    const float4* w24 = reinterpret_cast<const float4*>(w2);
#pragma unroll 4
    for (int c = 0; c < 128; ++c) {
        float4 wv = __ldg(&w24[c * 16 + tt]);
#pragma unroll
        for (int i = 0; i < 4; ++i) {
            float h = hsf[(r0b + i) * 132 + c];
            a2[i][0] += h * wv.x; a2[i][1] += h * wv.y;
            a2[i][2] += h * wv.z; a2[i][3] += h * wv.w;
        }
    }
    __syncthreads();   // all hs reads done before ls overwrites
#pragma unroll
    for (int i = 0; i < 4; ++i)
        *reinterpret_cast<float4*>(&ls[(r0b + i) * 68 + t0]) =
            make_float4(a2[i][0], a2[i][1], a2[i][2], a2[i][3]);
    __syncthreads();

    if (tx < 64) {
        int row = row0 + tx;
        const float* lr = ls + tx * 68;
        float m = -1e30f;
#pragma unroll 4
        for (int t = 0; t < 64; ++t) m = fmaxf(m, lr[t]);
        float s = 0.f;
#pragma unroll 4
        for (int t = 0; t < 64; ++t) s += expf(lr[t] - m);
        float inv = 1.f / s;
#pragma unroll 4
        for (int t = 0; t < 64; ++t)
            g_attn[t * B_TOTAL + row] = expf(lr[t] - m) * inv * (0.3f * resw[t]);
    }
}

// ================= kernel B: fused trees =================
// CTA = 64 rows, 128 threads. Loops 64 trees: logits GEMM (64x64x512) ->
// sigmoid -> routing products -> leaf reduction -> weighted accumulate -> softmax.
__global__ __launch_bounds__(128) void k_trees(
    const float* __restrict__ tree_w,
    const float* __restrict__ tree_b,
    const float* __restrict__ tree_temp,
    const float* __restrict__ leaf_values,
    float* __restrict__ out)
{
    __shared__ __align__(16) char smem[17408 * 2 + 3072];
    float4* xs4   = reinterpret_cast<float4*>(smem);            // [64][17] quads
    float*  dec_s = reinterpret_cast<float*>(smem);             // [64][68] floats (alias xs4)
    float4* ws4   = reinterpret_cast<float4*>(smem + 17408);    // [64][17] quads
    float*  leaf_s = reinterpret_cast<float*>(smem + 34816);    // [64][12] floats

    const int tx = threadIdx.x;
    const int row0 = blockIdx.x * 64;
    const int nt = tx & 15, rt = tx >> 4;   // 16 node-groups x 8 row-groups
    const int n0 = nt * 4,  r0 = rt * 8;    // 4 nodes, 8 rows per thread

    const float4* xc4 = reinterpret_cast<const float4*>(g_xc);
    const float4* tw4 = reinterpret_cast<const float4*>(tree_w);

    int miss[8];
#pragma unroll
    for (int i = 0; i < 8; ++i) miss[i] = g_missing[row0 + r0 + i];

    float pred[NCLS];
#pragma unroll
    for (int c = 0; c < NCLS; ++c) pred[c] = 0.f;

    for (int t = 0; t < NTREE; ++t) {
        // leaf values for this tree: 64 x 10 (pitch 12)
#pragma unroll
        for (int j = 0; j < 5; ++j) {
            int idx = tx + 128 * j;
            int L = idx / 10, c = idx - L * 10;
            leaf_s[L * 12 + c] = leaf_values[t * 640 + idx];
        }
        float invtemp = 1.f / tree_temp[t];

        float acc[8][4];
#pragma unroll
        for (int i = 0; i < 8; ++i)
#pragma unroll
            for (int j = 0; j < 4; ++j) acc[i][j] = 0.f;

        for (int kc = 0; kc < 8; ++kc) {     // K chunks of 64 (16 quads)
#pragma unroll
            for (int j = 0; j < 8; ++j) {    // xs: 64 rows x 16 quads
                int idx = tx + 128 * j;
                int r = idx >> 4, q = idx & 15;
                xs4[r * 17 + q] = xc4[(row0 + r) * 128 + kc * 16 + q];
            }
#pragma unroll
            for (int j = 0; j < 8; ++j) {    // ws: 64 nodes (63 real) x 16 quads
                int idx = tx + 128 * j;
                int n = idx >> 4, q = idx & 15;
                float4 v = make_float4(0.f, 0.f, 0.f, 0.f);
                if (n < NNODES) v = tw4[(t * NNODES + n) * 128 + kc * 16 + q];
                ws4[n * 17 + q] = v;
            }
            __syncthreads();
#pragma unroll
            for (int kq = 0; kq < 16; ++kq) {
                float4 w0 = ws4[(n0 + 0) * 17 + kq];
                float4 w1_ = ws4[(n0 + 1) * 17 + kq];
                float4 w2_ = ws4[(n0 + 2) * 17 + kq];
                float4 w3 = ws4[(n0 + 3) * 17 + kq];
#pragma unroll
                for (int i = 0; i < 8; ++i) {
                    float4 xv = xs4[(r0 + i) * 17 + kq];
                    acc[i][0] += xv.x * w0.x + xv.y * w0.y + xv.z * w0.z + xv.w * w0.w;
                    acc[i][1] += xv.x * w1_.x + xv.y * w1_.y + xv.z * w1_.z + xv.w * w1_.w;
                    acc[i][2] += xv.x * w2_.x + xv.y * w2_.y + xv.z * w2_.z + xv.w * w2_.w;
                    acc[i][3] += xv.x * w3.x + xv.y * w3.y + xv.z * w3.z + xv.w * w3.w;
                }
            }
            __syncthreads();
        }

        // sigmoid epilogue -> dec_s (aliases xs4; safe: past last sync all tile reads done)
        float bnv[4];
#pragma unroll
        for (int j = 0; j < 4; ++j)
            bnv[j] = (n0 + j < NNODES) ? tree_b[t * NNODES + n0 + j] : 0.f;
#pragma unroll
        for (int i = 0; i < 8; ++i) {
            float dv[4];
#pragma unroll
            for (int j = 0; j < 4; ++j) {
                float z = (acc[i][j] + bnv[j]) * invtemp;
                z = fminf(fmaxf(z, -30.f), 30.f);
                float e = __expf(-z);
                dv[j] = __fdividef(1.f, 1.f + e);
                if (miss[i]) dv[j] = 0.5f;
            }
            *reinterpret_cast<float4*>(&dec_s[(r0 + i) * 68 + n0]) =
                make_float4(dv[0], dv[1], dv[2], dv[3]);
        }
        __syncthreads();

        // routing + leaf reduction: one thread per row
        if (tx < 64) {
            const float* dp = dec_s + tx * 68;
            float ac = g_attn[t * B_TOTAL + row0 + tx];
            float r2[2], r4[4], r8[8], r16[16], r32[32];
            float d = dp[0];
            r2[0] = d; r2[1] = 1.f - d;
#pragma unroll
            for (int i = 0; i < 2; ++i) { d = dp[1 + i];  r4[i] = r2[i] * d;  r4[i + 2]  = r2[i] * (1.f - d); }
#pragma unroll
            for (int i = 0; i < 4; ++i) { d = dp[3 + i];  r8[i] = r4[i] * d;  r8[i + 4]  = r4[i] * (1.f - d); }
#pragma unroll
            for (int i = 0; i < 8; ++i) { d = dp[7 + i];  r16[i] = r8[i] * d; r16[i + 8] = r8[i] * (1.f - d); }
#pragma unroll
            for (int i = 0; i < 16; ++i){ d = dp[15 + i]; r32[i] = r16[i] * d; r32[i + 16] = r16[i] * (1.f - d); }
            float o[NCLS];
#pragma unroll
            for (int c = 0; c < NCLS; ++c) o[c] = 0.f;
#pragma unroll
            for (int i = 0; i < 32; ++i) {
                d = dp[31 + i];
                float pL = r32[i] * d;
                float pR = r32[i] * (1.f - d);
                const float* lL = leaf_s + i * 12;
                const float* lR = leaf_s + (i + 32) * 12;
#pragma unroll
                for (int c = 0; c < NCLS; ++c) o[c] += pL * lL[c] + pR * lR[c];
            }
#pragma unroll
            for (int c = 0; c < NCLS; ++c) pred[c] += ac * o[c];
        }
        __syncthreads();   // protect dec_s/leaf_s before next tree's loads
    }

    if (tx < 64) {
        int row = row0 + tx;
        float m = pred[0];
#pragma unroll
        for (int c = 1; c < NCLS; ++c) m = fmaxf(m, pred[c]);
        float e[NCLS], s = 0.f;
#pragma unroll
        for (int c = 0; c < NCLS; ++c) { e[c] = expf(pred[c] - m); s += e[c]; }
        float inv = 1.f / s;
#pragma unroll
        for (int c = 0; c < NCLS; ++c) out[row * NCLS + c] = e[c] * inv;
    }
}

// ================= launcher =================
extern "C" void kernel_launch(void* const* d_in, const int* in_sizes, int n_in,
                              void* d_out, int out_size) {
    const float* x     = (const float*)d_in[0];
    const float* w1    = (const float*)d_in[1];
    const float* b1    = (const float*)d_in[2];
    const float* gamma_ = (const float*)d_in[3];
    const float* beta_ = (const float*)d_in[4];
    const float* mean_ = (const float*)d_in[5];
    const float* var_  = (const float*)d_in[6];
    const float* w2    = (const float*)d_in[7];
    const float* b2    = (const float*)d_in[8];
    const float* tw    = (const float*)d_in[9];
    const float* tb    = (const float*)d_in[10];
    const float* ttmp  = (const float*)d_in[11];
    const float* lv    = (const float*)d_in[12];
    const float* rw    = (const float*)d_in[13];
    float* out = (float*)d_out;

    k_clean<<<B_TOTAL, 128>>>(x);
    k_attn<<<B_TOTAL / 64, 256>>>(x, w1, b1, gamma_, beta_, mean_, var_, w2, b2, rw);
    k_trees<<<B_TOTAL / 64, 128>>>(tw, tb, ttmp, lv, out);
}

// round 5
// speedup vs baseline: 4.8800x; 4.8800x over previous
#include <cuda_runtime.h>
#include <cuda_bf16.h>
#include <cstdint>
#include <math.h>

#define B_TOTAL 16384
#define NTREE 64
#define NNODES 63
#define NCLS 10

// fragment-ordered packed operands
__device__ unsigned char g_xf[128 * 8 * 32768]; // [tile128][kc8][hi16K|lo16K]
__device__ unsigned char g_wf[64 * 8 * 16384];  // [tree][kc8][hi8K|lo8K]
__device__ int g_missing[B_TOTAL];
__device__ float g_attn[NTREE * B_TOTAL];

__device__ __forceinline__ uint32_t smem_u32(const void* p) {
    uint32_t a;
    asm("{ .reg .u64 t; cvta.to.shared.u64 t, %1; cvt.u32.u64 %0, t; }" : "=r"(a) : "l"(p));
    return a;
}
#define CP16(s, g) asm volatile("cp.async.cg.shared.global [%0], [%1], 16;" :: "r"(s), "l"(g))
#define CPCOMMIT() asm volatile("cp.async.commit_group;")
#define CPWAIT1() asm volatile("cp.async.wait_group 1;")
#define CPWAIT0() asm volatile("cp.async.wait_group 0;")
#define MMA(c, a, b) asm volatile( \
    "mma.sync.aligned.m16n8k16.row.col.f32.bf16.bf16.f32 " \
    "{%0,%1,%2,%3},{%4,%5,%6,%7},{%8,%9},{%0,%1,%2,%3};" \
    : "+f"((c)[0]), "+f"((c)[1]), "+f"((c)[2]), "+f"((c)[3]) \
    : "r"((a).x), "r"((a).y), "r"((a).z), "r"((a).w), "r"((b).x), "r"((b).y))

// smem layout for k_trees
#define OFF_X 0u          // 2 x 32768
#define OFF_W 65536u      // 2 x 16384
#define OFF_LG 98304u     // 128 x 72 floats = 36864
#define OFF_LEAF 135168u  // 4 x 640 x 4 = 10240
#define OFF_TB 145408u    // 4 x 64 x 4 = 1024
#define OFF_IT 146432u    // 16
#define SMEM_SZ 146464u

// ---------- prep x: NaN-clean + bf16 hi/lo in A-fragment order ----------
__global__ __launch_bounds__(256) void k_prep_x(const float* __restrict__ x) {
    __shared__ __align__(16) unsigned char stage[32768]; // hi 16K | lo 16K
    const int tile = blockIdx.x >> 3, kc = blockIdx.x & 7, tid = threadIdx.x;
    for (int e = tid; e < 8192; e += 256) {
        int r = e >> 6, j = e & 63;
        int row = tile * 128 + r;
        float v = x[row * 512 + kc * 64 + j];
        if (v != v) { v = 0.f; atomicOr(&g_missing[row], 1); }
        __nv_bfloat16 h = __float2bfloat16(v);
        __nv_bfloat16 l = __float2bfloat16(v - __bfloat162float(h));
        int mtile = r >> 4, row16 = r & 15, g = row16 & 7, half = row16 >> 3;
        int kstep = j >> 4, kk = j & 15, tg = (kk >> 1) & 3, khalf = kk >> 3, klo = kk & 1;
        int t = g * 4 + tg, reg = half + 2 * khalf;
        uint32_t off = (uint32_t)(((kstep * 8 + mtile) * 32 + t) * 16 + reg * 4 + klo * 2);
        *(__nv_bfloat16*)(stage + off) = h;
        *(__nv_bfloat16*)(stage + 16384 + off) = l;
    }
    __syncthreads();
    uint4* dst = (uint4*)(g_xf + (size_t)blockIdx.x * 32768);
    const uint4* src = (const uint4*)stage;
    for (int e = tid; e < 2048; e += 256) dst[e] = src[e];
}

// ---------- prep w: bf16 hi/lo in B-fragment order ----------
__global__ __launch_bounds__(256) void k_prep_w(const float* __restrict__ tw) {
    __shared__ __align__(16) unsigned char stage[16384]; // hi 8K | lo 8K
    const int tree = blockIdx.x >> 3, kc = blockIdx.x & 7, tid = threadIdx.x;
    for (int e = tid; e < 4096; e += 256) {
        int n = e >> 6, j = e & 63;
        float v = (n < NNODES) ? tw[((size_t)(tree * NNODES + n)) * 512 + kc * 64 + j] : 0.f;
        __nv_bfloat16 h = __float2bfloat16(v);
        __nv_bfloat16 l = __float2bfloat16(v - __bfloat162float(h));
        int ntile = n >> 3, g = n & 7;
        int kstep = j >> 4, kk = j & 15, tg = (kk >> 1) & 3, regidx = kk >> 3, klo = kk & 1;
        int t = g * 4 + tg;
        uint32_t off = (uint32_t)(((kstep * 8 + ntile) * 32 + t) * 8 + regidx * 4 + klo * 2);
        *(__nv_bfloat16*)(stage + off) = h;
        *(__nv_bfloat16*)(stage + 8192 + off) = l;
    }
    __syncthreads();
    uint4* dst = (uint4*)(g_wf + (size_t)blockIdx.x * 16384);
    const uint4* src = (const uint4*)stage;
    for (int e = tid; e < 1024; e += 256) dst[e] = src[e];
}

// ---------- attention (SIMT, unchanged from passing version) ----------
__global__ __launch_bounds__(256) void k_attn(
    const float* __restrict__ x, const float* __restrict__ w1, const float* __restrict__ b1,
    const float* __restrict__ gamma_, const float* __restrict__ beta_,
    const float* __restrict__ mean_, const float* __restrict__ var_,
    const float* __restrict__ w2, const float* __restrict__ b2, const float* __restrict__ resw)
{
    __shared__ __align__(16) char smem[33792];
    float4* xs4 = (float4*)smem; float* xsf = (float*)smem;
    float4* w1s4 = (float4*)(smem + 9216);
    float4* hs4 = (float4*)smem; float* hsf = (float*)smem; float* ls = (float*)smem;
    const int tx = threadIdx.x, row0 = blockIdx.x * 64;
    const int ct = tx & 15, rt = tx >> 4, c0 = ct * 8, r0 = rt * 4;
    float acc[4][8];
#pragma unroll
    for (int i = 0; i < 4; ++i)
#pragma unroll
        for (int j = 0; j < 8; ++j) acc[i][j] = 0.f;
    const float4* x4 = (const float4*)x;
    const float4* w14 = (const float4*)w1;
    for (int kc = 0; kc < 16; ++kc) {
#pragma unroll
        for (int j = 0; j < 2; ++j) {
            int idx = tx + 256 * j, r = idx >> 3, q = idx & 7;
            xs4[r * 9 + q] = x4[(row0 + r) * 128 + kc * 8 + q];
        }
#pragma unroll
        for (int j = 0; j < 4; ++j) {
            int idx = tx + 256 * j, k = idx >> 5, cq = idx & 31;
            w1s4[k * 33 + cq] = w14[(kc * 32 + k) * 32 + cq];
        }
        __syncthreads();
#pragma unroll 4
        for (int kk = 0; kk < 32; ++kk) {
            float4 b0 = w1s4[kk * 33 + ct * 2], b1q = w1s4[kk * 33 + ct * 2 + 1];
#pragma unroll
            for (int i = 0; i < 4; ++i) {
                float a = xsf[(r0 + i) * 36 + kk];
                acc[i][0] += a * b0.x; acc[i][1] += a * b0.y; acc[i][2] += a * b0.z; acc[i][3] += a * b0.w;
                acc[i][4] += a * b1q.x; acc[i][5] += a * b1q.y; acc[i][6] += a * b1q.z; acc[i][7] += a * b1q.w;
            }
        }
        __syncthreads();
    }
    float sc[8], sh[8], bb[8];
#pragma unroll
    for (int j = 0; j < 8; ++j) {
        int c = c0 + j;
        float s = gamma_[c] * rsqrtf(var_[c] + 1e-5f);
        sc[j] = s; sh[j] = beta_[c] - mean_[c] * s; bb[j] = b1[c];
    }
#pragma unroll
    for (int i = 0; i < 4; ++i) {
        float h[8];
#pragma unroll
        for (int j = 0; j < 8; ++j) { float v = fmaxf(acc[i][j] + bb[j], 0.f); h[j] = v * sc[j] + sh[j]; }
        hs4[(r0 + i) * 33 + ct * 2] = make_float4(h[0], h[1], h[2], h[3]);
        hs4[(r0 + i) * 33 + ct * 2 + 1] = make_float4(h[4], h[5], h[6], h[7]);
    }
    __syncthreads();
    const int tt = tx & 15, rt2 = tx >> 4, t0 = tt * 4, r0b = rt2 * 4;
    float a2[4][4];
#pragma unroll
    for (int i = 0; i < 4; ++i)
#pragma unroll
        for (int j = 0; j < 4; ++j) a2[i][j] = b2[t0 + j];
    const float4* w24 = (const float4*)w2;
#pragma unroll 4
    for (int c = 0; c < 128; ++c) {
        float4 wv = __ldg(&w24[c * 16 + tt]);
#pragma unroll
        for (int i = 0; i < 4; ++i) {
            float h = hsf[(r0b + i) * 132 + c];
            a2[i][0] += h * wv.x; a2[i][1] += h * wv.y; a2[i][2] += h * wv.z; a2[i][3] += h * wv.w;
        }
    }
    __syncthreads();
#pragma unroll
    for (int i = 0; i < 4; ++i)
        *(float4*)&ls[(r0b + i) * 68 + t0] = make_float4(a2[i][0], a2[i][1], a2[i][2], a2[i][3]);
    __syncthreads();
    if (tx < 64) {
        int row = row0 + tx;
        const float* lr = ls + tx * 68;
        float m = -1e30f, s = 0.f;
#pragma unroll 4
        for (int t = 0; t < 64; ++t) m = fmaxf(m, lr[t]);
#pragma unroll 4
        for (int t = 0; t < 64; ++t) s += expf(lr[t] - m);
        float inv = 1.f / s;
#pragma unroll 4
        for (int t = 0; t < 64; ++t) g_attn[t * B_TOTAL + row] = expf(lr[t] - m) * inv * (0.3f * resw[t]);
    }
}

// ---------- k_trees: mma.sync bf16 hi/lo, G=4 trees per group ----------
__global__ __launch_bounds__(256, 1) void k_trees(
    const float* __restrict__ tree_b, const float* __restrict__ tree_temp,
    const float* __restrict__ leaf_values, float* __restrict__ out)
{
    extern __shared__ __align__(16) char smp[];
    const uint32_t sm = smem_u32(smp);
    const int tid = threadIdx.x, lane = tid & 31, wid = tid >> 5;
    const int wm = wid & 3, wn = wid >> 2;        // warp tile: rows wm*32, cols wn*32
    const int row = tid & 127, half = tid >> 7;   // epilogue mapping
    const int rowg = blockIdx.x * 128 + row;
    float* lg = (float*)(smp + OFF_LG);           // [128][72]
    float* leaf_s = (float*)(smp + OFF_LEAF);
    float* tb_s = (float*)(smp + OFF_TB);
    float* it_s = (float*)(smp + OFF_IT);
    const int miss = g_missing[rowg];

    float pred[NCLS];
#pragma unroll
    for (int c = 0; c < NCLS; ++c) pred[c] = 0.f;

    const unsigned char* xbase = g_xf + (size_t)blockIdx.x * 8 * 32768;

    for (int grp = 0; grp < 16; ++grp) {
        // per-group metadata (epilogue-only; synced before use)
        {
            int g = tid >> 6, n = tid & 63;
            tb_s[tid] = (n < NNODES) ? tree_b[(grp * 4 + g) * NNODES + n] : 0.f;
            if (tid < 4) it_s[tid] = 1.f / tree_temp[grp * 4 + tid];
        }
        float acc[4][2][4][4];
#pragma unroll
        for (int g = 0; g < 4; ++g)
#pragma unroll
            for (int mi = 0; mi < 2; ++mi)
#pragma unroll
                for (int ni = 0; ni < 4; ++ni)
#pragma unroll
                    for (int q = 0; q < 4; ++q) acc[g][mi][ni][q] = 0.f;

        // issue loads for iter i (kc = i>>2, g = i&3)
        auto issue = [&](int i) {
            int kc = i >> 2, g = i & 3;
            const unsigned char* wsrc = g_wf + (size_t)((grp * 4 + g) * 8 + kc) * 16384;
            uint32_t wdst = sm + OFF_W + (uint32_t)(i & 1) * 16384;
#pragma unroll
            for (int j = 0; j < 4; ++j) {
                int ch = tid + 256 * j;
                CP16(wdst + ch * 16, wsrc + ch * 16);
            }
            if (g == 0) {
                const unsigned char* xsrc = xbase + (size_t)kc * 32768;
                uint32_t xdst = sm + OFF_X + (uint32_t)(kc & 1) * 32768;
#pragma unroll
                for (int j = 0; j < 8; ++j) {
                    int ch = tid + 256 * j;
                    CP16(xdst + ch * 16, xsrc + ch * 16);
                }
            }
        };
        issue(0);
        // leaf values for this group's 4 trees (needed only at epilogue)
        {
            const unsigned char* lsrc = (const unsigned char*)leaf_values + (size_t)grp * 10240;
#pragma unroll
            for (int j = 0; j < 3; ++j) {
                int ch = tid + 256 * j;
                if (ch < 640) CP16(sm + OFF_LEAF + ch * 16, lsrc + ch * 16);
            }
        }
        CPCOMMIT();

        for (int i = 0; i < 32; ++i) {
            if (i + 1 < 32) { issue(i + 1); CPCOMMIT(); CPWAIT1(); }
            else CPWAIT0();
            __syncthreads();
            const int kc = i >> 2, g = i & 3;
            const char* bx = smp + OFF_X + (kc & 1) * 32768;
            const char* bw = smp + OFF_W + (i & 1) * 16384;
#pragma unroll
            for (int ks = 0; ks < 4; ++ks) {
                uint4 ah[2], al[2];
                uint2 bh[4], bl[4];
#pragma unroll
                for (int mi = 0; mi < 2; ++mi) {
                    uint32_t o = (uint32_t)(((ks * 8 + wm * 2 + mi) * 32 + lane) * 16);
                    ah[mi] = *(const uint4*)(bx + o);
                    al[mi] = *(const uint4*)(bx + 16384 + o);
                }
#pragma unroll
                for (int ni = 0; ni < 4; ++ni) {
                    uint32_t o = (uint32_t)(((ks * 8 + wn * 4 + ni) * 32 + lane) * 8);
                    bh[ni] = *(const uint2*)(bw + o);
                    bl[ni] = *(const uint2*)(bw + 8192 + o);
                }
#pragma unroll
                for (int mi = 0; mi < 2; ++mi)
#pragma unroll
                    for (int ni = 0; ni < 4; ++ni) {
                        MMA(acc[g][mi][ni], ah[mi], bh[ni]);
                        MMA(acc[g][mi][ni], ah[mi], bl[ni]);
                        MMA(acc[g][mi][ni], al[mi], bh[ni]);
                    }
            }
            __syncthreads();
        }

        // ---- epilogue: 4 trees ----
        for (int g = 0; g < 4; ++g) {
            // c-frags -> logits smem
#pragma unroll
            for (int mi = 0; mi < 2; ++mi)
#pragma unroll
                for (int ni = 0; ni < 4; ++ni) {
                    int r0 = (wm * 2 + mi) * 16 + (lane >> 2);
                    int c0 = wn * 32 + ni * 8 + (lane & 3) * 2;
                    *(float2*)&lg[r0 * 72 + c0] = make_float2(acc[g][mi][ni][0], acc[g][mi][ni][1]);
                    *(float2*)&lg[(r0 + 8) * 72 + c0] = make_float2(acc[g][mi][ni][2], acc[g][mi][ni][3]);
                }
            __syncthreads();
            // sigmoid in place: half h handles nodes h*32 .. h*32+31
            {
                float invt = it_s[g];
                const float* tb = tb_s + g * 64;
#pragma unroll
                for (int j = 0; j < 32; ++j) {
                    int n = half * 32 + j;
                    if (n < NNODES) {
                        float z = (lg[row * 72 + n] + tb[n]) * invt;
                        z = fminf(fmaxf(z, -30.f), 30.f);
                        float d = __fdividef(1.f, 1.f + __expf(-z));
                        lg[row * 72 + n] = miss ? 0.5f : d;
                    }
                }
            }
            __syncthreads();
            // routing + leaf reduce: halves split the 16 leaf-pair indices
            {
                const float* dp = lg + row * 72;
                float d0 = dp[0], d1 = dp[1], d2 = dp[2];
                float r2[2], r4[4], r8[8];
                r2[0] = d0; r2[1] = 1.f - d0;
                r4[0] = r2[0] * d1; r4[2] = r2[0] - r4[0];
                r4[1] = r2[1] * d2; r4[3] = r2[1] - r4[1];
#pragma unroll
                for (int j = 0; j < 4; ++j) {
                    float d = dp[3 + j];
                    r8[j] = r4[j] * d; r8[j + 4] = r4[j] - r8[j];
                }
                float o[NCLS];
#pragma unroll
                for (int c = 0; c < NCLS; ++c) o[c] = 0.f;
                const float* lf = leaf_s + g * 640;
#pragma unroll
                for (int j = 0; j < 16; ++j) {
                    int i = half * 16 + j;
                    float f3 = dp[7 + (i & 7)];  if ((i >> 3) & 1) f3 = 1.f - f3;
                    float f4 = dp[15 + (i & 15)]; if (half) f4 = 1.f - f4;
                    float rr = r8[i & 7] * f3 * f4;
                    float d5 = dp[31 + i];
                    float pL = rr * d5, pR = rr - pL;
                    const float* lL = lf + i * 10;
                    const float* lR = lf + (i + 32) * 10;
#pragma unroll
                    for (int c = 0; c < NCLS; ++c) o[c] += pL * lL[c] + pR * lR[c];
                }
                float at = g_attn[(grp * 4 + g) * B_TOTAL + rowg];
#pragma unroll
                for (int c = 0; c < NCLS; ++c) pred[c] += at * o[c];
            }
            __syncthreads();
        }
    }

    // combine halves + softmax
    float* pred_s = lg; // reuse
    if (half == 1) {
#pragma unroll
        for (int c = 0; c < NCLS; ++c) pred_s[row * 10 + c] = pred[c];
    }
    __syncthreads();
    if (half == 0) {
#pragma unroll
        for (int c = 0; c < NCLS; ++c) pred[c] += pred_s[row * 10 + c];
        float m = pred[0];
#pragma unroll
        for (int c = 1; c < NCLS; ++c) m = fmaxf(m, pred[c]);
        float e[NCLS], s = 0.f;
#pragma unroll
        for (int c = 0; c < NCLS; ++c) { e[c] = expf(pred[c] - m); s += e[c]; }
        float inv = 1.f / s;
#pragma unroll
        for (int c = 0; c < NCLS; ++c) out[rowg * 10 + c] = e[c] * inv;
    }
}

// ---------- launcher ----------
extern "C" void kernel_launch(void* const* d_in, const int* in_sizes, int n_in,
                              void* d_out, int out_size) {
    const float* x = (const float*)d_in[0];
    const float* w1 = (const float*)d_in[1];
    const float* b1 = (const float*)d_in[2];
    const float* gm = (const float*)d_in[3];
    const float* bt = (const float*)d_in[4];
    const float* mn = (const float*)d_in[5];
    const float* vr = (const float*)d_in[6];
    const float* w2 = (const float*)d_in[7];
    const float* b2 = (const float*)d_in[8];
    const float* tw = (const float*)d_in[9];
    const float* tb = (const float*)d_in[10];
    const float* tt = (const float*)d_in[11];
    const float* lv = (const float*)d_in[12];
    const float* rw = (const float*)d_in[13];
    static int done = 0;
    if (!done) {
        cudaFuncSetAttribute(k_trees, cudaFuncAttributeMaxDynamicSharedMemorySize, SMEM_SZ);
        done = 1;
    }
    k_prep_x<<<1024, 256>>>(x);
    k_prep_w<<<512, 256>>>(tw);
    k_attn<<<B_TOTAL / 64, 256>>>(x, w1, b1, gm, bt, mn, vr, w2, b2, rw);
    k_trees<<<128, 256, SMEM_SZ>>>(tb, tt, lv, (float*)d_out);
}

// round 7
// speedup vs baseline: 6.7839x; 1.3902x over previous
#include <cuda_runtime.h>
#include <cuda_bf16.h>
#include <cstdint>
#include <math.h>

#define B_TOTAL 16384
#define NTREE 64
#define NNODES 63
#define NCLS 10

__device__ unsigned char g_xf[128 * 8 * 32768]; // [tile128][kc8][hi16K|lo16K] A-frag order
__device__ unsigned char g_wf[64 * 8 * 16384];  // [tree][kc8][hi8K|lo8K]     B-frag order
__device__ int g_missing[B_TOTAL];
__device__ float g_attn[NTREE * B_TOTAL];

__device__ __forceinline__ uint32_t smem_u32(const void* p) {
    uint32_t a;
    asm("{ .reg .u64 t; cvta.to.shared.u64 t, %1; cvt.u32.u64 %0, t; }" : "=r"(a) : "l"(p));
    return a;
}
#define CP16(s, g) asm volatile("cp.async.cg.shared.global [%0], [%1], 16;" :: "r"(s), "l"(g))
#define CPCOMMIT() asm volatile("cp.async.commit_group;")
#define CPWAIT1() asm volatile("cp.async.wait_group 1;")
#define CPWAIT0() asm volatile("cp.async.wait_group 0;")
#define MMA(c, a, b) asm volatile( \
    "mma.sync.aligned.m16n8k16.row.col.f32.bf16.bf16.f32 " \
    "{%0,%1,%2,%3},{%4,%5,%6,%7},{%8,%9},{%0,%1,%2,%3};" \
    : "+f"((c)[0]), "+f"((c)[1]), "+f"((c)[2]), "+f"((c)[3]) \
    : "r"((a).x), "r"((a).y), "r"((a).z), "r"((a).w), "r"((b).x), "r"((b).y))

// smem layout
#define OFF_X 0u          // 2 x 32768
#define OFF_W 65536u      // 2 x (2 trees x 16384)
#define OFF_LG 131072u    // 128 x 72 floats = 36864
#define OFF_LEAF 167936u  // 2 x 5120
#define SMEM_SZ 178176u

// ---------- prep x: NaN-clean + bf16 hi/lo in A-fragment order ----------
__global__ __launch_bounds__(256) void k_prep_x(const float* __restrict__ x) {
    __shared__ __align__(16) unsigned char stage[32768];
    const int tile = blockIdx.x >> 3, kc = blockIdx.x & 7, tid = threadIdx.x;
    for (int e = tid; e < 8192; e += 256) {
        int r = e >> 6, j = e & 63;
        int row = tile * 128 + r;
        float v = x[row * 512 + kc * 64 + j];
        if (v != v) { v = 0.f; atomicOr(&g_missing[row], 1); }
        __nv_bfloat16 h = __float2bfloat16(v);
        __nv_bfloat16 l = __float2bfloat16(v - __bfloat162float(h));
        int mtile = r >> 4, row16 = r & 15, g = row16 & 7, half = row16 >> 3;
        int kstep = j >> 4, kk = j & 15, tg = (kk >> 1) & 3, khalf = kk >> 3, klo = kk & 1;
        int t = g * 4 + tg, reg = half + 2 * khalf;
        uint32_t off = (uint32_t)(((kstep * 8 + mtile) * 32 + t) * 16 + reg * 4 + klo * 2);
        *(__nv_bfloat16*)(stage + off) = h;
        *(__nv_bfloat16*)(stage + 16384 + off) = l;
    }
    __syncthreads();
    uint4* dst = (uint4*)(g_xf + (size_t)blockIdx.x * 32768);
    const uint4* src = (const uint4*)stage;
    for (int e = tid; e < 2048; e += 256) dst[e] = src[e];
}

// ---------- prep w: bf16 hi/lo in B-fragment order ----------
__global__ __launch_bounds__(256) void k_prep_w(const float* __restrict__ tw) {
    __shared__ __align__(16) unsigned char stage[16384];
    const int tree = blockIdx.x >> 3, kc = blockIdx.x & 7, tid = threadIdx.x;
    for (int e = tid; e < 4096; e += 256) {
        int n = e >> 6, j = e & 63;
        float v = (n < NNODES) ? tw[((size_t)(tree * NNODES + n)) * 512 + kc * 64 + j] : 0.f;
        __nv_bfloat16 h = __float2bfloat16(v);
        __nv_bfloat16 l = __float2bfloat16(v - __bfloat162float(h));
        int ntile = n >> 3, g = n & 7;
        int kstep = j >> 4, kk = j & 15, tg = (kk >> 1) & 3, regidx = kk >> 3, klo = kk & 1;
        int t = g * 4 + tg;
        uint32_t off = (uint32_t)(((kstep * 8 + ntile) * 32 + t) * 8 + regidx * 4 + klo * 2);
        *(__nv_bfloat16*)(stage + off) = h;
        *(__nv_bfloat16*)(stage + 8192 + off) = l;
    }
    __syncthreads();
    uint4* dst = (uint4*)(g_wf + (size_t)blockIdx.x * 16384);
    const uint4* src = (const uint4*)stage;
    for (int e = tid; e < 1024; e += 256) dst[e] = src[e];
}

// ---------- attention (SIMT) ----------
__global__ __launch_bounds__(256) void k_attn(
    const float* __restrict__ x, const float* __restrict__ w1, const float* __restrict__ b1,
    const float* __restrict__ gamma_, const float* __restrict__ beta_,
    const float* __restrict__ mean_, const float* __restrict__ var_,
    const float* __restrict__ w2, const float* __restrict__ b2, const float* __restrict__ resw)
{
    __shared__ __align__(16) char smem[33792];
    float4* xs4 = (float4*)smem; float* xsf = (float*)smem;
    float4* w1s4 = (float4*)(smem + 9216);
    float4* hs4 = (float4*)smem; float* hsf = (float*)smem; float* ls = (float*)smem;
    const int tx = threadIdx.x, row0 = blockIdx.x * 64;
    const int ct = tx & 15, rt = tx >> 4, c0 = ct * 8, r0 = rt * 4;
    float acc[4][8];
#pragma unroll
    for (int i = 0; i < 4; ++i)
#pragma unroll
        for (int j = 0; j < 8; ++j) acc[i][j] = 0.f;
    const float4* x4 = (const float4*)x;
    const float4* w14 = (const float4*)w1;
    for (int kc = 0; kc < 16; ++kc) {
#pragma unroll
        for (int j = 0; j < 2; ++j) {
            int idx = tx + 256 * j, r = idx >> 3, q = idx & 7;
            xs4[r * 9 + q] = x4[(row0 + r) * 128 + kc * 8 + q];
        }
#pragma unroll
        for (int j = 0; j < 4; ++j) {
            int idx = tx + 256 * j, k = idx >> 5, cq = idx & 31;
            w1s4[k * 33 + cq] = w14[(kc * 32 + k) * 32 + cq];
        }
        __syncthreads();
#pragma unroll 4
        for (int kk = 0; kk < 32; ++kk) {
            float4 b0 = w1s4[kk * 33 + ct * 2], b1q = w1s4[kk * 33 + ct * 2 + 1];
#pragma unroll
            for (int i = 0; i < 4; ++i) {
                float a = xsf[(r0 + i) * 36 + kk];
                acc[i][0] += a * b0.x; acc[i][1] += a * b0.y; acc[i][2] += a * b0.z; acc[i][3] += a * b0.w;
                acc[i][4] += a * b1q.x; acc[i][5] += a * b1q.y; acc[i][6] += a * b1q.z; acc[i][7] += a * b1q.w;
            }
        }
        __syncthreads();
    }
    float sc[8], sh[8], bb[8];
#pragma unroll
    for (int j = 0; j < 8; ++j) {
        int c = c0 + j;
        float s = gamma_[c] * rsqrtf(var_[c] + 1e-5f);
        sc[j] = s; sh[j] = beta_[c] - mean_[c] * s; bb[j] = b1[c];
    }
#pragma unroll
    for (int i = 0; i < 4; ++i) {
        float h[8];
#pragma unroll
        for (int j = 0; j < 8; ++j) { float v = fmaxf(acc[i][j] + bb[j], 0.f); h[j] = v * sc[j] + sh[j]; }
        hs4[(r0 + i) * 33 + ct * 2] = make_float4(h[0], h[1], h[2], h[3]);
        hs4[(r0 + i) * 33 + ct * 2 + 1] = make_float4(h[4], h[5], h[6], h[7]);
    }
    __syncthreads();
    const int tt = tx & 15, rt2 = tx >> 4, t0 = tt * 4, r0b = rt2 * 4;
    float a2[4][4];
#pragma unroll
    for (int i = 0; i < 4; ++i)
#pragma unroll
        for (int j = 0; j < 4; ++j) a2[i][j] = b2[t0 + j];
    const float4* w24 = (const float4*)w2;
#pragma unroll 4
    for (int c = 0; c < 128; ++c) {
        float4 wv = __ldg(&w24[c * 16 + tt]);
#pragma unroll
        for (int i = 0; i < 4; ++i) {
            float h = hsf[(r0b + i) * 132 + c];
            a2[i][0] += h * wv.x; a2[i][1] += h * wv.y; a2[i][2] += h * wv.z; a2[i][3] += h * wv.w;
        }
    }
    __syncthreads();
#pragma unroll
    for (int i = 0; i < 4; ++i)
        *(float4*)&ls[(r0b + i) * 68 + t0] = make_float4(a2[i][0], a2[i][1], a2[i][2], a2[i][3]);
    __syncthreads();
    if (tx < 64) {
        int row = row0 + tx;
        const float* lr = ls + tx * 68;
        float m = -1e30f, s = 0.f;
#pragma unroll 4
        for (int t = 0; t < 64; ++t) m = fmaxf(m, lr[t]);
#pragma unroll 4
        for (int t = 0; t < 64; ++t) s += expf(lr[t] - m);
        float inv = 1.f / s;
#pragma unroll 4
        for (int t = 0; t < 64; ++t) g_attn[t * B_TOTAL + row] = expf(lr[t] - m) * inv * (0.3f * resw[t]);
    }
}

// ---------- k_trees: 2 trees/group, 1 tree per warp, no spills ----------
__global__ __launch_bounds__(256, 1) void k_trees(
    const float* __restrict__ tree_b, const float* __restrict__ tree_temp,
    const float* __restrict__ leaf_values, float* __restrict__ out)
{
    extern __shared__ __align__(16) char smp[];
    const uint32_t sm = smem_u32(smp);
    const int tid = threadIdx.x, lane = tid & 31, wid = tid >> 5;
    const int wt = wid & 1, wm = wid >> 1;        // tree-within-group, M warp (rows wm*32)
    const int row = tid & 127, half = tid >> 7;
    const int rowg = blockIdx.x * 128 + row;
    float* lg = (float*)(smp + OFF_LG);           // [128][72]
    const int miss = g_missing[rowg];

    float pred[NCLS];
#pragma unroll
    for (int c = 0; c < NCLS; ++c) pred[c] = 0.f;

    const unsigned char* xbase = g_xf + (size_t)blockIdx.x * 8 * 32768;

    auto issue = [&](int s) {
        const int grp = s >> 3, kc = s & 7;
        const uint32_t buf = (uint32_t)(s & 1);
        const unsigned char* xsrc = xbase + (size_t)kc * 32768;
        const uint32_t xdst = sm + OFF_X + buf * 32768;
#pragma unroll
        for (int j = 0; j < 8; ++j) {
            int ch = tid + 256 * j;
            CP16(xdst + ch * 16, xsrc + ch * 16);
        }
        const unsigned char* wsrc0 = g_wf + (size_t)((grp * 2) * 8 + kc) * 16384;
        const uint32_t wdst = sm + OFF_W + buf * 32768;
#pragma unroll
        for (int j = 0; j < 4; ++j) {
            int ch = tid + 256 * j;
            CP16(wdst + ch * 16, wsrc0 + ch * 16);
            CP16(wdst + 16384 + ch * 16, wsrc0 + 8 * 16384 + ch * 16);
        }
        if (kc == 0) {
            // 5120 bytes = 320 x 16B chunks: two strided passes (256-thread block!)
            const unsigned char* lsrc = (const unsigned char*)leaf_values + (size_t)grp * 5120;
            uint32_t ldst = sm + OFF_LEAF + (uint32_t)(grp & 1) * 5120;
            CP16(ldst + tid * 16, lsrc + tid * 16);
            if (tid < 64) CP16(ldst + (tid + 256) * 16, lsrc + (tid + 256) * 16);
        }
    };

    float acc[2][8][4];
#pragma unroll
    for (int mi = 0; mi < 2; ++mi)
#pragma unroll
        for (int ni = 0; ni < 8; ++ni)
#pragma unroll
            for (int q = 0; q < 4; ++q) acc[mi][ni][q] = 0.f;

    issue(0);
    CPCOMMIT();

    for (int s = 0; s < 256; ++s) {
        if (s + 1 < 256) { issue(s + 1); CPCOMMIT(); CPWAIT1(); }
        else CPWAIT0();
        __syncthreads();
        const char* bx = smp + OFF_X + (s & 1) * 32768;
        const char* bw = smp + OFF_W + (s & 1) * 32768 + wt * 16384;
#pragma unroll
        for (int ks = 0; ks < 4; ++ks) {
            uint4 ah[2], al[2];
#pragma unroll
            for (int mi = 0; mi < 2; ++mi) {
                uint32_t o = (uint32_t)(((ks * 8 + wm * 2 + mi) * 32 + lane) * 16);
                ah[mi] = *(const uint4*)(bx + o);
                al[mi] = *(const uint4*)(bx + 16384 + o);
            }
#pragma unroll
            for (int ni = 0; ni < 8; ++ni) {
                uint32_t o = (uint32_t)(((ks * 8 + ni) * 32 + lane) * 8);
                uint2 bh = *(const uint2*)(bw + o);
                uint2 bl = *(const uint2*)(bw + 8192 + o);
#pragma unroll
                for (int mi = 0; mi < 2; ++mi) {
                    MMA(acc[mi][ni], ah[mi], bh);
                    MMA(acc[mi][ni], ah[mi], bl);
                    MMA(acc[mi][ni], al[mi], bh);
                }
            }
        }
        __syncthreads();

        if ((s & 7) == 7) {
            const int grp = s >> 3;
            // ---- epilogue for 2 trees ----
            for (int tt = 0; tt < 2; ++tt) {
                const int t = grp * 2 + tt;
                if (wt == tt) {
#pragma unroll
                    for (int mi = 0; mi < 2; ++mi)
#pragma unroll
                        for (int ni = 0; ni < 8; ++ni) {
                            int r0 = wm * 32 + mi * 16 + (lane >> 2);
                            int c0 = ni * 8 + (lane & 3) * 2;
                            *(float2*)&lg[r0 * 72 + c0] = make_float2(acc[mi][ni][0], acc[mi][ni][1]);
                            *(float2*)&lg[(r0 + 8) * 72 + c0] = make_float2(acc[mi][ni][2], acc[mi][ni][3]);
                        }
                }
                __syncthreads();
                {
                    float invt = 1.f / tree_temp[t];
#pragma unroll
                    for (int j = 0; j < 32; ++j) {
                        int n = half * 32 + j;
                        if (n < NNODES) {
                            float z = (lg[row * 72 + n] + tree_b[t * NNODES + n]) * invt;
                            z = fminf(fmaxf(z, -30.f), 30.f);
                            float d = __fdividef(1.f, 1.f + __expf(-z));
                            lg[row * 72 + n] = miss ? 0.5f : d;
                        }
                    }
                }
                __syncthreads();
                {
                    const float* dp = lg + row * 72;
                    const float* lf = (const float*)(smp + OFF_LEAF + (grp & 1) * 5120) + tt * 640;
                    float d0 = dp[0], d1 = dp[1], d2 = dp[2];
                    float r2[2], r4[4], r8[8];
                    r2[0] = d0; r2[1] = 1.f - d0;
                    r4[0] = r2[0] * d1; r4[2] = r2[0] - r4[0];
                    r4[1] = r2[1] * d2; r4[3] = r2[1] - r4[1];
#pragma unroll
                    for (int j = 0; j < 4; ++j) {
                        float d = dp[3 + j];
                        r8[j] = r4[j] * d; r8[j + 4] = r4[j] - r8[j];
                    }
                    float o[NCLS];
#pragma unroll
                    for (int c = 0; c < NCLS; ++c) o[c] = 0.f;
#pragma unroll
                    for (int j = 0; j < 16; ++j) {
                        int i = half * 16 + j;
                        float f3 = dp[7 + (i & 7)];  if ((i >> 3) & 1) f3 = 1.f - f3;
                        float f4 = dp[15 + (i & 15)]; if (half) f4 = 1.f - f4;
                        float rr = r8[i & 7] * f3 * f4;
                        float d5 = dp[31 + i];
                        float pL = rr * d5, pR = rr - pL;
                        const float* lL = lf + i * 10;
                        const float* lR = lf + (i + 32) * 10;
#pragma unroll
                        for (int c = 0; c < NCLS; ++c) o[c] += pL * lL[c] + pR * lR[c];
                    }
                    float at = g_attn[t * B_TOTAL + rowg];
#pragma unroll
                    for (int c = 0; c < NCLS; ++c) pred[c] += at * o[c];
                }
                __syncthreads();
            }
#pragma unroll
            for (int mi = 0; mi < 2; ++mi)
#pragma unroll
                for (int ni = 0; ni < 8; ++ni)
#pragma unroll
                    for (int q = 0; q < 4; ++q) acc[mi][ni][q] = 0.f;
        }
    }

    // combine halves + softmax
    float* pred_s = lg;
    if (half == 1) {
#pragma unroll
        for (int c = 0; c < NCLS; ++c) pred_s[row * 10 + c] = pred[c];
    }
    __syncthreads();
    if (half == 0) {
#pragma unroll
        for (int c = 0; c < NCLS; ++c) pred[c] += pred_s[row * 10 + c];
        float m = pred[0];
#pragma unroll
        for (int c = 1; c < NCLS; ++c) m = fmaxf(m, pred[c]);
        float e[NCLS], s = 0.f;
#pragma unroll
        for (int c = 0; c < NCLS; ++c) { e[c] = expf(pred[c] - m); s += e[c]; }
        float inv = 1.f / s;
#pragma unroll
        for (int c = 0; c < NCLS; ++c) out[rowg * 10 + c] = e[c] * inv;
    }
}

// ---------- launcher ----------
extern "C" void kernel_launch(void* const* d_in, const int* in_sizes, int n_in,
                              void* d_out, int out_size) {
    const float* x = (const float*)d_in[0];
    const float* w1 = (const float*)d_in[1];
    const float* b1 = (const float*)d_in[2];
    const float* gm = (const float*)d_in[3];
    const float* bt = (const float*)d_in[4];
    const float* mn = (const float*)d_in[5];
    const float* vr = (const float*)d_in[6];
    const float* w2 = (const float*)d_in[7];
    const float* b2 = (const float*)d_in[8];
    const float* tw = (const float*)d_in[9];
    const float* tb = (const float*)d_in[10];
    const float* tt = (const float*)d_in[11];
    const float* lv = (const float*)d_in[12];
    const float* rw = (const float*)d_in[13];
    cudaFuncSetAttribute(k_trees, cudaFuncAttributeMaxDynamicSharedMemorySize, SMEM_SZ);
    k_prep_x<<<1024, 256>>>(x);
    k_prep_w<<<512, 256>>>(tw);
    k_attn<<<B_TOTAL / 64, 256>>>(x, w1, b1, gm, bt, mn, vr, w2, b2, rw);
    k_trees<<<128, 256, SMEM_SZ>>>(tb, tt, lv, (float*)d_out);
}

// round 8
// speedup vs baseline: 6.9650x; 1.0267x over previous
#include <cuda_runtime.h>
#include <cuda_bf16.h>
#include <cstdint>
#include <math.h>

#define B_TOTAL 16384
#define NTREE 64
#define NNODES 63
#define NCLS 10

__device__ unsigned char g_xf[128 * 8 * 32768]; // [tile128][kc8][hi16K|lo16K] A-frag order
__device__ unsigned char g_wf[64 * 8 * 16384];  // [tree][kc8][hi8K|lo8K]     B-frag order
__device__ int g_missing[B_TOTAL];
__device__ float g_attn[NTREE * B_TOTAL];

__device__ __forceinline__ uint32_t smem_u32(const void* p) {
    uint32_t a;
    asm("{ .reg .u64 t; cvta.to.shared.u64 t, %1; cvt.u32.u64 %0, t; }" : "=r"(a) : "l"(p));
    return a;
}
#define CP16(s, g) asm volatile("cp.async.cg.shared.global [%0], [%1], 16;" :: "r"(s), "l"(g))
#define CPCOMMIT() asm volatile("cp.async.commit_group;")
#define CPWAIT1() asm volatile("cp.async.wait_group 1;")
#define CPWAIT0() asm volatile("cp.async.wait_group 0;")
#define MMA(c, a, b) asm volatile( \
    "mma.sync.aligned.m16n8k16.row.col.f32.bf16.bf16.f32 " \
    "{%0,%1,%2,%3},{%4,%5,%6,%7},{%8,%9},{%0,%1,%2,%3};" \
    : "+f"((c)[0]), "+f"((c)[1]), "+f"((c)[2]), "+f"((c)[3]) \
    : "r"((a).x), "r"((a).y), "r"((a).z), "r"((a).w), "r"((b).x), "r"((b).y))

// smem layout
#define OFF_X 0u          // 2 x 32768
#define OFF_W 65536u      // 2 x (2 trees x 16384)
#define OFF_LG 131072u    // logits 128x72 floats / pred staging
#define OFF_LEAF 167936u  // 2 x 5120
#define SMEM_SZ 178176u

// ---------- prep x: NaN-clean + bf16 hi/lo in A-fragment order ----------
__global__ __launch_bounds__(256) void k_prep_x(const float* __restrict__ x) {
    __shared__ __align__(16) unsigned char stage[32768];
    const int tile = blockIdx.x >> 3, kc = blockIdx.x & 7, tid = threadIdx.x;
    for (int e = tid; e < 8192; e += 256) {
        int r = e >> 6, j = e & 63;
        int row = tile * 128 + r;
        float v = x[row * 512 + kc * 64 + j];
        if (v != v) { v = 0.f; atomicOr(&g_missing[row], 1); }
        __nv_bfloat16 h = __float2bfloat16(v);
        __nv_bfloat16 l = __float2bfloat16(v - __bfloat162float(h));
        int mtile = r >> 4, row16 = r & 15, g = row16 & 7, half = row16 >> 3;
        int kstep = j >> 4, kk = j & 15, tg = (kk >> 1) & 3, khalf = kk >> 3, klo = kk & 1;
        int t = g * 4 + tg, reg = half + 2 * khalf;
        uint32_t off = (uint32_t)(((kstep * 8 + mtile) * 32 + t) * 16 + reg * 4 + klo * 2);
        *(__nv_bfloat16*)(stage + off) = h;
        *(__nv_bfloat16*)(stage + 16384 + off) = l;
    }
    __syncthreads();
    uint4* dst = (uint4*)(g_xf + (size_t)blockIdx.x * 32768);
    const uint4* src = (const uint4*)stage;
    for (int e = tid; e < 2048; e += 256) dst[e] = src[e];
}

// ---------- prep w: bf16 hi/lo in B-fragment order ----------
__global__ __launch_bounds__(256) void k_prep_w(const float* __restrict__ tw) {
    __shared__ __align__(16) unsigned char stage[16384];
    const int tree = blockIdx.x >> 3, kc = blockIdx.x & 7, tid = threadIdx.x;
    for (int e = tid; e < 4096; e += 256) {
        int n = e >> 6, j = e & 63;
        float v = (n < NNODES) ? tw[((size_t)(tree * NNODES + n)) * 512 + kc * 64 + j] : 0.f;
        __nv_bfloat16 h = __float2bfloat16(v);
        __nv_bfloat16 l = __float2bfloat16(v - __bfloat162float(h));
        int ntile = n >> 3, g = n & 7;
        int kstep = j >> 4, kk = j & 15, tg = (kk >> 1) & 3, regidx = kk >> 3, klo = kk & 1;
        int t = g * 4 + tg;
        uint32_t off = (uint32_t)(((kstep * 8 + ntile) * 32 + t) * 8 + regidx * 4 + klo * 2);
        *(__nv_bfloat16*)(stage + off) = h;
        *(__nv_bfloat16*)(stage + 8192 + off) = l;
    }
    __syncthreads();
    uint4* dst = (uint4*)(g_wf + (size_t)blockIdx.x * 16384);
    const uint4* src = (const uint4*)stage;
    for (int e = tid; e < 1024; e += 256) dst[e] = src[e];
}

// ---------- attention (SIMT) ----------
__global__ __launch_bounds__(256) void k_attn(
    const float* __restrict__ x, const float* __restrict__ w1, const float* __restrict__ b1,
    const float* __restrict__ gamma_, const float* __restrict__ beta_,
    const float* __restrict__ mean_, const float* __restrict__ var_,
    const float* __restrict__ w2, const float* __restrict__ b2, const float* __restrict__ resw)
{
    __shared__ __align__(16) char smem[33792];
    float4* xs4 = (float4*)smem; float* xsf = (float*)smem;
    float4* w1s4 = (float4*)(smem + 9216);
    float4* hs4 = (float4*)smem; float* hsf = (float*)smem; float* ls = (float*)smem;
    const int tx = threadIdx.x, row0 = blockIdx.x * 64;
    const int ct = tx & 15, rt = tx >> 4, c0 = ct * 8, r0 = rt * 4;
    float acc[4][8];
#pragma unroll
    for (int i = 0; i < 4; ++i)
#pragma unroll
        for (int j = 0; j < 8; ++j) acc[i][j] = 0.f;
    const float4* x4 = (const float4*)x;
    const float4* w14 = (const float4*)w1;
    for (int kc = 0; kc < 16; ++kc) {
#pragma unroll
        for (int j = 0; j < 2; ++j) {
            int idx = tx + 256 * j, r = idx >> 3, q = idx & 7;
            xs4[r * 9 + q] = x4[(row0 + r) * 128 + kc * 8 + q];
        }
#pragma unroll
        for (int j = 0; j < 4; ++j) {
            int idx = tx + 256 * j, k = idx >> 5, cq = idx & 31;
            w1s4[k * 33 + cq] = w14[(kc * 32 + k) * 32 + cq];
        }
        __syncthreads();
#pragma unroll 4
        for (int kk = 0; kk < 32; ++kk) {
            float4 b0 = w1s4[kk * 33 + ct * 2], b1q = w1s4[kk * 33 + ct * 2 + 1];
#pragma unroll
            for (int i = 0; i < 4; ++i) {
                float a = xsf[(r0 + i) * 36 + kk];
                acc[i][0] += a * b0.x; acc[i][1] += a * b0.y; acc[i][2] += a * b0.z; acc[i][3] += a * b0.w;
                acc[i][4] += a * b1q.x; acc[i][5] += a * b1q.y; acc[i][6] += a * b1q.z; acc[i][7] += a * b1q.w;
            }
        }
        __syncthreads();
    }
    float sc[8], sh[8], bb[8];
#pragma unroll
    for (int j = 0; j < 8; ++j) {
        int c = c0 + j;
        float s = gamma_[c] * rsqrtf(var_[c] + 1e-5f);
        sc[j] = s; sh[j] = beta_[c] - mean_[c] * s; bb[j] = b1[c];
    }
#pragma unroll
    for (int i = 0; i < 4; ++i) {
        float h[8];
#pragma unroll
        for (int j = 0; j < 8; ++j) { float v = fmaxf(acc[i][j] + bb[j], 0.f); h[j] = v * sc[j] + sh[j]; }
        hs4[(r0 + i) * 33 + ct * 2] = make_float4(h[0], h[1], h[2], h[3]);
        hs4[(r0 + i) * 33 + ct * 2 + 1] = make_float4(h[4], h[5], h[6], h[7]);
    }
    __syncthreads();
    const int tt = tx & 15, rt2 = tx >> 4, t0 = tt * 4, r0b = rt2 * 4;
    float a2[4][4];
#pragma unroll
    for (int i = 0; i < 4; ++i)
#pragma unroll
        for (int j = 0; j < 4; ++j) a2[i][j] = b2[t0 + j];
    const float4* w24 = (const float4*)w2;
#pragma unroll 4
    for (int c = 0; c < 128; ++c) {
        float4 wv = __ldg(&w24[c * 16 + tt]);
#pragma unroll
        for (int i = 0; i < 4; ++i) {
            float h = hsf[(r0b + i) * 132 + c];
            a2[i][0] += h * wv.x; a2[i][1] += h * wv.y; a2[i][2] += h * wv.z; a2[i][3] += h * wv.w;
        }
    }
    __syncthreads();
#pragma unroll
    for (int i = 0; i < 4; ++i)
        *(float4*)&ls[(r0b + i) * 68 + t0] = make_float4(a2[i][0], a2[i][1], a2[i][2], a2[i][3]);
    __syncthreads();
    if (tx < 64) {
        int row = row0 + tx;
        const float* lr = ls + tx * 68;
        float m = -1e30f, s = 0.f;
#pragma unroll 4
        for (int t = 0; t < 64; ++t) m = fmaxf(m, lr[t]);
#pragma unroll 4
        for (int t = 0; t < 64; ++t) s += expf(lr[t] - m);
        float inv = 1.f / s;
#pragma unroll 4
        for (int t = 0; t < 64; ++t) g_attn[t * B_TOTAL + row] = expf(lr[t] - m) * inv * (0.3f * resw[t]);
    }
}

// ---------- k_trees: 512 threads, 16 warps = (2 trees x 4 M x 2 N-halves) ----------
__global__ __launch_bounds__(512, 1) void k_trees(
    const float* __restrict__ tree_b, const float* __restrict__ tree_temp,
    const float* __restrict__ leaf_values, float* __restrict__ out)
{
    extern __shared__ __align__(16) char smp[];
    const uint32_t sm = smem_u32(smp);
    const int tid = threadIdx.x, lane = tid & 31, wid = tid >> 5;
    const int wt = wid & 1;                 // tree within group
    const int wm = (wid >> 1) & 3;          // M tile (32 rows)
    const int wn = (wid >> 3) & 1;          // N half (4 ni each)
    const int row = tid & 127, part = tid >> 7;   // epilogue: 4 threads/row
    const int rowg = blockIdx.x * 128 + row;
    float* lg = (float*)(smp + OFF_LG);           // [128][72]
    const int miss = g_missing[rowg];

    float pred[NCLS];
#pragma unroll
    for (int c = 0; c < NCLS; ++c) pred[c] = 0.f;

    const unsigned char* xbase = g_xf + (size_t)blockIdx.x * 8 * 32768;

    auto issue = [&](int s) {
        const int grp = s >> 3, kc = s & 7;
        const uint32_t buf = (uint32_t)(s & 1);
        const unsigned char* xsrc = xbase + (size_t)kc * 32768;
        const uint32_t xdst = sm + OFF_X + buf * 32768;
#pragma unroll
        for (int j = 0; j < 4; ++j) {
            int ch = tid + 512 * j;
            CP16(xdst + ch * 16, xsrc + ch * 16);
        }
        const unsigned char* wsrc0 = g_wf + (size_t)((grp * 2) * 8 + kc) * 16384;
        const uint32_t wdst = sm + OFF_W + buf * 32768;
#pragma unroll
        for (int j = 0; j < 2; ++j) {
            int ch = tid + 512 * j;
            CP16(wdst + ch * 16, wsrc0 + ch * 16);
            CP16(wdst + 16384 + ch * 16, wsrc0 + 8 * 16384 + ch * 16);
        }
        if (kc == 0) {
            const unsigned char* lsrc = (const unsigned char*)leaf_values + (size_t)grp * 5120;
            uint32_t ldst = sm + OFF_LEAF + (uint32_t)(grp & 1) * 5120;
            if (tid < 320) CP16(ldst + tid * 16, lsrc + tid * 16);
        }
    };

    float acc[2][4][4];
#pragma unroll
    for (int mi = 0; mi < 2; ++mi)
#pragma unroll
        for (int ni = 0; ni < 4; ++ni)
#pragma unroll
            for (int q = 0; q < 4; ++q) acc[mi][ni][q] = 0.f;

    issue(0);
    CPCOMMIT();

    for (int s = 0; s < 256; ++s) {
        if (s + 1 < 256) { issue(s + 1); CPCOMMIT(); CPWAIT1(); }
        else CPWAIT0();
        __syncthreads();
        const char* bx = smp + OFF_X + (s & 1) * 32768;
        const char* bw = smp + OFF_W + (s & 1) * 32768 + wt * 16384;
#pragma unroll
        for (int ks = 0; ks < 4; ++ks) {
            uint4 ah[2], al[2];
#pragma unroll
            for (int mi = 0; mi < 2; ++mi) {
                uint32_t o = (uint32_t)(((ks * 8 + wm * 2 + mi) * 32 + lane) * 16);
                ah[mi] = *(const uint4*)(bx + o);
                al[mi] = *(const uint4*)(bx + 16384 + o);
            }
#pragma unroll
            for (int ni = 0; ni < 4; ++ni) {
                uint32_t o = (uint32_t)(((ks * 8 + wn * 4 + ni) * 32 + lane) * 8);
                uint2 bh = *(const uint2*)(bw + o);
                uint2 bl = *(const uint2*)(bw + 8192 + o);
#pragma unroll
                for (int mi = 0; mi < 2; ++mi) {
                    MMA(acc[mi][ni], ah[mi], bh);
                    MMA(acc[mi][ni], ah[mi], bl);
                    MMA(acc[mi][ni], al[mi], bh);
                }
            }
        }
        __syncthreads();

        if ((s & 7) == 7) {
            const int grp = s >> 3;
            for (int tt = 0; tt < 2; ++tt) {
                const int t = grp * 2 + tt;
                if (wt == tt) {
#pragma unroll
                    for (int mi = 0; mi < 2; ++mi)
#pragma unroll
                        for (int ni = 0; ni < 4; ++ni) {
                            int r0 = wm * 32 + mi * 16 + (lane >> 2);
                            int c0 = wn * 32 + ni * 8 + (lane & 3) * 2;
                            *(float2*)&lg[r0 * 72 + c0] = make_float2(acc[mi][ni][0], acc[mi][ni][1]);
                            *(float2*)&lg[(r0 + 8) * 72 + c0] = make_float2(acc[mi][ni][2], acc[mi][ni][3]);
                        }
                }
                __syncthreads();
                {
                    float invt = 1.f / tree_temp[t];
#pragma unroll
                    for (int j = 0; j < 16; ++j) {
                        int n = part * 16 + j;
                        if (n < NNODES) {
                            float z = (lg[row * 72 + n] + tree_b[t * NNODES + n]) * invt;
                            z = fminf(fmaxf(z, -30.f), 30.f);
                            float d = __fdividef(1.f, 1.f + __expf(-z));
                            lg[row * 72 + n] = miss ? 0.5f : d;
                        }
                    }
                }
                __syncthreads();
                {
                    const float* dp = lg + row * 72;
                    const float* lf = (const float*)(smp + OFF_LEAF + (grp & 1) * 5120) + tt * 640;
                    float d0 = dp[0], d1 = dp[1], d2 = dp[2];
                    float r2[2], r4[4], r8[8];
                    r2[0] = d0; r2[1] = 1.f - d0;
                    r4[0] = r2[0] * d1; r4[2] = r2[0] - r4[0];
                    r4[1] = r2[1] * d2; r4[3] = r2[1] - r4[1];
#pragma unroll
                    for (int j = 0; j < 4; ++j) {
                        float d = dp[3 + j];
                        r8[j] = r4[j] * d; r8[j + 4] = r4[j] - r8[j];
                    }
                    float o[NCLS];
#pragma unroll
                    for (int c = 0; c < NCLS; ++c) o[c] = 0.f;
#pragma unroll
                    for (int j = 0; j < 8; ++j) {
                        int i = part * 8 + j;
                        float f3 = dp[7 + (i & 7)];   if ((i >> 3) & 1) f3 = 1.f - f3;
                        float f4 = dp[15 + (i & 15)]; if ((i >> 4) & 1) f4 = 1.f - f4;
                        float rr = r8[i & 7] * f3 * f4;
                        float d5 = dp[31 + i];
                        float pL = rr * d5, pR = rr - pL;
                        const float* lL = lf + i * 10;
                        const float* lR = lf + (i + 32) * 10;
#pragma unroll
                        for (int c = 0; c < NCLS; ++c) o[c] += pL * lL[c] + pR * lR[c];
                    }
                    float at = g_attn[t * B_TOTAL + rowg];
#pragma unroll
                    for (int c = 0; c < NCLS; ++c) pred[c] += at * o[c];
                }
                __syncthreads();
            }
#pragma unroll
            for (int mi = 0; mi < 2; ++mi)
#pragma unroll
                for (int ni = 0; ni < 4; ++ni)
#pragma unroll
                    for (int q = 0; q < 4; ++q) acc[mi][ni][q] = 0.f;
        }
    }

    // combine 4 parts + softmax
    float* pred_s = lg;   // 4 x 128 x 10 = 20K < 36K
#pragma unroll
    for (int c = 0; c < NCLS; ++c) pred_s[part * 1280 + row * 10 + c] = pred[c];
    __syncthreads();
    if (tid < 128) {
#pragma unroll
        for (int c = 0; c < NCLS; ++c)
            pred[c] = pred_s[row * 10 + c] + pred_s[1280 + row * 10 + c]
                    + pred_s[2560 + row * 10 + c] + pred_s[3840 + row * 10 + c];
        float m = pred[0];
#pragma unroll
        for (int c = 1; c < NCLS; ++c) m = fmaxf(m, pred[c]);
        float e[NCLS], s = 0.f;
#pragma unroll
        for (int c = 0; c < NCLS; ++c) { e[c] = expf(pred[c] - m); s += e[c]; }
        float inv = 1.f / s;
#pragma unroll
        for (int c = 0; c < NCLS; ++c) out[rowg * 10 + c] = e[c] * inv;
    }
}

// ---------- launcher ----------
extern "C" void kernel_launch(void* const* d_in, const int* in_sizes, int n_in,
                              void* d_out, int out_size) {
    const float* x = (const float*)d_in[0];
    const float* w1 = (const float*)d_in[1];
    const float* b1 = (const float*)d_in[2];
    const float* gm = (const float*)d_in[3];
    const float* bt = (const float*)d_in[4];
    const float* mn = (const float*)d_in[5];
    const float* vr = (const float*)d_in[6];
    const float* w2 = (const float*)d_in[7];
    const float* b2 = (const float*)d_in[8];
    const float* tw = (const float*)d_in[9];
    const float* tb = (const float*)d_in[10];
    const float* tt = (const float*)d_in[11];
    const float* lv = (const float*)d_in[12];
    const float* rw = (const float*)d_in[13];
    cudaFuncSetAttribute(k_trees, cudaFuncAttributeMaxDynamicSharedMemorySize, SMEM_SZ);
    k_prep_x<<<1024, 256>>>(x);
    k_prep_w<<<512, 256>>>(tw);
    k_attn<<<B_TOTAL / 64, 256>>>(x, w1, b1, gm, bt, mn, vr, w2, b2, rw);
    k_trees<<<128, 512, SMEM_SZ>>>(tb, tt, lv, (float*)d_out);
}